// round 1
// baseline (speedup 1.0000x reference)
#include <cuda_runtime.h>
#include <math.h>

#define BATCH 16
#define TLEN  2048
#define LRELU_SLOPE 0.02f
#define GN_EPS 1e-5

// ---------------- scratch (no allocations allowed) ----------------
__device__ float  g_bufA[BATCH * 1024 * TLEN];   // 134 MB
__device__ float  g_bufB[BATCH * 512  * TLEN];   // 67 MB
__device__ float  g_bufC[BATCH * 640  * TLEN];   // 84 MB (concat buffers)
__device__ float  g_yv  [BATCH * 128  * TLEN];   // speaker cond
__device__ float  g_z   [BATCH * 128  * TLEN];   // latent
__device__ float  g_spkn[64 * 128];
__device__ float  g_cbn [512 * 128];
__device__ float  g_wt0 [1024 * 256 * 5];        // transposed+flipped decoder weights
__device__ float  g_wt1 [1024 * 640 * 5];
__device__ float  g_wt2 [39   * 640 * 5];
__device__ double g_stats[2 * BATCH];

// ---------------- small helpers ----------------
__global__ void normalize_rows_kernel(const float* __restrict__ in,
                                      float* __restrict__ out) {
    // one block per row of 128, 128 threads
    int r = blockIdx.x, tid = threadIdx.x;
    float v = in[r * 128 + tid];
    __shared__ float sh[128];
    sh[tid] = v * v;
    __syncthreads();
    for (int off = 64; off > 0; off >>= 1) {
        if (tid < off) sh[tid] += sh[tid + off];
        __syncthreads();
    }
    out[r * 128 + tid] = v * rsqrtf(sh[0] + 1e-12f);
}

__global__ void gather_yv_kernel(const int* __restrict__ y,
                                 const float* __restrict__ spkn,
                                 float* __restrict__ yv) {
    int b = blockIdx.z, d = blockIdx.y;
    int t = blockIdx.x * 256 + threadIdx.x;
    int idx = y[b * TLEN + t];
    yv[((size_t)b * 128 + d) * TLEN + t] = spkn[idx * 128 + d];
}

__global__ void copy_yv_kernel(const float* __restrict__ yv,
                               float* __restrict__ cat, int off, int Ctot) {
    int b = blockIdx.z, d = blockIdx.y;
    int t = blockIdx.x * 256 + threadIdx.x;
    cat[((size_t)b * Ctot + off + d) * TLEN + t] =
        yv[((size_t)b * 128 + d) * TLEN + t];
}

// ConvTranspose weight [CI][CO][K] -> conv weight [CO][CI][K] with k flipped
__global__ void wtrans_kernel(const float* __restrict__ W,
                              float* __restrict__ Wt, int CI, int CO) {
    int idx = blockIdx.x * 256 + threadIdx.x;
    int total = CI * CO * 5;
    if (idx >= total) return;
    int k  = idx % 5;
    int o  = (idx / 5) % CO;
    int ci = idx / (5 * CO);
    Wt[((size_t)o * CI + ci) * 5 + (4 - k)] = W[idx];
}

// ---------------- conv1d (stride 1, same padding) ----------------
// Block computes a 64(out-ch) x 64(time) tile for one batch sample.
// 256 threads, each owns a 4x4 register tile. K-dim looped in CI chunks of 8.
template <int K>
__global__ void conv1d_kernel(const float* __restrict__ X,
                              const float* __restrict__ W,
                              const float* __restrict__ bias,
                              float* __restrict__ Y,
                              int CI, int CO) {
    const int OT = 64, TT = 64, CIT = 8;
    const int PAD = (K - 1) / 2;
    const int XROW = TT + K - 1;

    __shared__ float Xs[CIT][XROW];
    __shared__ float Ws[CIT][K][OT];

    int b  = blockIdx.z;
    int t0 = blockIdx.x * TT;
    int o0 = blockIdx.y * OT;
    int tid = threadIdx.x;
    int tx = tid & 15, ty = tid >> 4;

    const float* Xb = X + (size_t)b * CI * TLEN;
    float acc[4][4] = {};

    for (int cb = 0; cb < CI; cb += CIT) {
        // stage input tile (with halo, zero-padded)
        for (int i = tid; i < CIT * XROW; i += 256) {
            int ci = i / XROW, tt = i % XROW;
            int gci = cb + ci;
            int gt  = t0 + tt - PAD;
            float v = 0.f;
            if (gci < CI && gt >= 0 && gt < TLEN) v = Xb[(size_t)gci * TLEN + gt];
            Xs[ci][tt] = v;
        }
        // stage weights: map i = oo*(CIT*K) + ci*K + k -> contiguous global reads
        for (int i = tid; i < CIT * K * OT; i += 256) {
            int oo = i / (CIT * K);
            int r  = i % (CIT * K);
            int ci = r / K;
            int k  = r % K;
            int gci = cb + ci, go = o0 + oo;
            float v = 0.f;
            if (gci < CI && go < CO) v = W[((size_t)go * CI + gci) * K + k];
            Ws[ci][k][oo] = v;
        }
        __syncthreads();

#pragma unroll
        for (int ci = 0; ci < CIT; ci++) {
#pragma unroll
            for (int k = 0; k < K; k++) {
                float xv[4], wv[4];
#pragma unroll
                for (int j = 0; j < 4; j++) xv[j] = Xs[ci][tx + 16 * j + k];
#pragma unroll
                for (int i = 0; i < 4; i++) wv[i] = Ws[ci][k][ty + 16 * i];
#pragma unroll
                for (int i = 0; i < 4; i++)
#pragma unroll
                    for (int j = 0; j < 4; j++) acc[i][j] += wv[i] * xv[j];
            }
        }
        __syncthreads();
    }

#pragma unroll
    for (int i = 0; i < 4; i++) {
        int o = o0 + ty + 16 * i;
        if (o >= CO) continue;
        float bv = bias[o];
#pragma unroll
        for (int j = 0; j < 4; j++) {
            int t = t0 + tx + 16 * j;
            if (t < TLEN) Y[((size_t)b * CO + o) * TLEN + t] = acc[i][j] + bv;
        }
    }
}

// ---------------- GroupNorm(1) two-pass ----------------
__global__ void zero_stats_kernel() {
    if (threadIdx.x < 2 * BATCH) g_stats[threadIdx.x] = 0.0;
}

__global__ void gn_stats_kernel(const float* __restrict__ X, int N) {
    int b = blockIdx.y;
    const float* Xb = X + (size_t)b * N;
    double s = 0.0, s2 = 0.0;
    for (int i = blockIdx.x * blockDim.x + threadIdx.x; i < N;
         i += gridDim.x * blockDim.x) {
        float v = Xb[i];
        s += v;
        s2 += (double)v * v;
    }
    __shared__ double sh1[256], sh2[256];
    int tid = threadIdx.x;
    sh1[tid] = s; sh2[tid] = s2;
    __syncthreads();
    for (int off = 128; off > 0; off >>= 1) {
        if (tid < off) { sh1[tid] += sh1[tid + off]; sh2[tid] += sh2[tid + off]; }
        __syncthreads();
    }
    if (tid == 0) {
        atomicAdd(&g_stats[2 * b],     sh1[0]);
        atomicAdd(&g_stats[2 * b + 1], sh2[0]);
    }
}

__global__ void gn_lrelu_kernel(float* __restrict__ X,
                                const float* __restrict__ g,
                                const float* __restrict__ bt, int C) {
    int b = blockIdx.z, c = blockIdx.y;
    int t = blockIdx.x * 256 + threadIdx.x;
    double N = (double)C * TLEN;
    double mean = g_stats[2 * b] / N;
    double var  = g_stats[2 * b + 1] / N - mean * mean;
    float rstd = (float)rsqrt(var + GN_EPS);
    float sc = g[c] * rstd;
    float sh = bt[c] - (float)mean * sc;
    size_t idx = ((size_t)b * C + c) * TLEN + t;
    float yv = X[idx] * sc + sh;
    X[idx] = yv >= 0.f ? yv : LRELU_SLOPE * yv;
}

// GroupNorm over 2H channels then GLU -> cat buffer channels [0,H)
__global__ void gn_glu_kernel(const float* __restrict__ X,
                              const float* __restrict__ g,
                              const float* __restrict__ bt,
                              float* __restrict__ cat, int H, int Ctot) {
    int b = blockIdx.z, c = blockIdx.y;
    int t = blockIdx.x * 256 + threadIdx.x;
    int C = 2 * H;
    double N = (double)C * TLEN;
    double mean = g_stats[2 * b] / N;
    double var  = g_stats[2 * b + 1] / N - mean * mean;
    float rstd = (float)rsqrt(var + GN_EPS);
    float m = (float)mean;
    float a  = X[((size_t)b * C + c)     * TLEN + t];
    float gv = X[((size_t)b * C + c + H) * TLEN + t];
    float na = (a  - m) * rstd * g[c]     + bt[c];
    float ng = (gv - m) * rstd * g[c + H] + bt[c + H];
    cat[((size_t)b * Ctot + c) * TLEN + t] = na / (1.f + expf(-ng));
}

// ---------------- VQ: argmax_k <z, cbn_k> ; write cbn[k*] into cat ----------------
// Normalizing z is unnecessary for the argmax (positive scalar). Codebook is
// pre-normalized in g_cbn. One warp per (b,t); 8 warps per block.
__global__ void vq_kernel(const float* __restrict__ z,
                          const float* __restrict__ cbn,
                          float* __restrict__ cat, int Ctot) {
    __shared__ float zs[8][128];
    int warp = threadIdx.x >> 5, lane = threadIdx.x & 31;
    int pos = blockIdx.x * 8 + warp;
    int b = pos / TLEN, t = pos % TLEN;

    for (int d = lane; d < 128; d += 32)
        zs[warp][d] = z[((size_t)b * 128 + d) * TLEN + t];
    __syncwarp();

    const float4* zs4 = (const float4*)zs[warp];
    float best = -1e30f;
    int bk = 0;
    for (int kk = 0; kk < 16; kk++) {
        int k = kk * 32 + lane;
        const float4* cb4 = (const float4*)(cbn + (size_t)k * 128);
        float s = 0.f;
#pragma unroll
        for (int d4 = 0; d4 < 32; d4++) {
            float4 zv = zs4[d4], cv = cb4[d4];
            s += zv.x * cv.x + zv.y * cv.y + zv.z * cv.z + zv.w * cv.w;
        }
        if (s > best || (s == best && k < bk)) { best = s; bk = k; }
    }
    for (int off = 16; off > 0; off >>= 1) {
        float ob = __shfl_down_sync(0xffffffff, best, off);
        int   ok = __shfl_down_sync(0xffffffff, bk,   off);
        if (ob > best || (ob == best && ok < bk)) { best = ob; bk = ok; }
    }
    bk = __shfl_sync(0xffffffff, bk, 0);
    for (int d = lane; d < 128; d += 32)
        cat[((size_t)b * Ctot + d) * TLEN + t] = cbn[(size_t)bk * 128 + d];
}

// ---------------- host orchestration ----------------
static void launch_conv5(const float* X, const float* W, const float* b,
                         float* Y, int CI, int CO) {
    dim3 grid(TLEN / 64, (CO + 63) / 64, BATCH);
    conv1d_kernel<5><<<grid, 256>>>(X, W, b, Y, CI, CO);
}

static void launch_gn_stats(const float* X, int C) {
    zero_stats_kernel<<<1, 32>>>();
    gn_stats_kernel<<<dim3(128, BATCH), 256>>>(X, C * TLEN);
}

extern "C" void kernel_launch(void* const* d_in, const int* in_sizes, int n_in,
                              void* d_out, int out_size) {
    const float* x    = (const float*)d_in[0];
    const int*   y    = (const int*)  d_in[1];
    const float* spk  = (const float*)d_in[2];
    const float* cb   = (const float*)d_in[3];
    const float *ew0 = (const float*)d_in[4],  *eb0 = (const float*)d_in[5];
    const float *eg0 = (const float*)d_in[6],  *et0 = (const float*)d_in[7];
    const float *ew1 = (const float*)d_in[8],  *eb1 = (const float*)d_in[9];
    const float *eg1 = (const float*)d_in[10], *et1 = (const float*)d_in[11];
    const float *ew2 = (const float*)d_in[12], *eb2 = (const float*)d_in[13];
    const float *eg2 = (const float*)d_in[14], *et2 = (const float*)d_in[15];
    const float *mw  = (const float*)d_in[16], *mb  = (const float*)d_in[17];
    const float *dw0 = (const float*)d_in[18], *db0 = (const float*)d_in[19];
    const float *dg0 = (const float*)d_in[20], *dt0 = (const float*)d_in[21];
    const float *dw1 = (const float*)d_in[22], *db1 = (const float*)d_in[23];
    const float *dg1 = (const float*)d_in[24], *dt1 = (const float*)d_in[25];
    const float *dw2 = (const float*)d_in[26], *db2 = (const float*)d_in[27];
    float* out = (float*)d_out;

    float *bufA, *bufB, *bufC, *yv, *z, *spkn, *cbn, *wt0, *wt1, *wt2;
    cudaGetSymbolAddress((void**)&bufA, g_bufA);
    cudaGetSymbolAddress((void**)&bufB, g_bufB);
    cudaGetSymbolAddress((void**)&bufC, g_bufC);
    cudaGetSymbolAddress((void**)&yv,   g_yv);
    cudaGetSymbolAddress((void**)&z,    g_z);
    cudaGetSymbolAddress((void**)&spkn, g_spkn);
    cudaGetSymbolAddress((void**)&cbn,  g_cbn);
    cudaGetSymbolAddress((void**)&wt0,  g_wt0);
    cudaGetSymbolAddress((void**)&wt1,  g_wt1);
    cudaGetSymbolAddress((void**)&wt2,  g_wt2);

    // prep: normalized embeddings/codebook, speaker gather, decoder weight flip
    normalize_rows_kernel<<<64, 128>>>(spk, spkn);
    normalize_rows_kernel<<<512, 128>>>(cb, cbn);
    gather_yv_kernel<<<dim3(TLEN / 256, 128, BATCH), 256>>>(y, spkn, yv);
    wtrans_kernel<<<(1024 * 256 * 5 + 255) / 256, 256>>>(dw0, wt0, 256, 1024);
    wtrans_kernel<<<(1024 * 640 * 5 + 255) / 256, 256>>>(dw1, wt1, 640, 1024);
    wtrans_kernel<<<(39 * 640 * 5 + 255) / 256, 256>>>(dw2, wt2, 640, 39);

    // ---- encoder ----
    launch_conv5(x, ew0, eb0, bufA, 39, 1024);
    launch_gn_stats(bufA, 1024);
    gn_lrelu_kernel<<<dim3(TLEN / 256, 1024, BATCH), 256>>>(bufA, eg0, et0, 1024);

    launch_conv5(bufA, ew1, eb1, bufB, 1024, 512);
    launch_gn_stats(bufB, 512);
    gn_lrelu_kernel<<<dim3(TLEN / 256, 512, BATCH), 256>>>(bufB, eg1, et1, 512);

    launch_conv5(bufB, ew2, eb2, bufA, 512, 512);
    launch_gn_stats(bufA, 512);
    gn_lrelu_kernel<<<dim3(TLEN / 256, 512, BATCH), 256>>>(bufA, eg2, et2, 512);

    // 1x1 conv to latent
    conv1d_kernel<1><<<dim3(TLEN / 64, 2, BATCH), 256>>>(bufA, mw, mb, z, 512, 128);

    // ---- VQ + concat speaker cond -> cat0 [B,256,T] ----
    vq_kernel<<<BATCH * TLEN / 8, 256>>>(z, cbn, bufC, 256);
    copy_yv_kernel<<<dim3(TLEN / 256, 128, BATCH), 256>>>(yv, bufC, 128, 256);

    // ---- decoder ----
    launch_conv5(bufC, wt0, db0, bufA, 256, 1024);
    launch_gn_stats(bufA, 1024);
    gn_glu_kernel<<<dim3(TLEN / 256, 512, BATCH), 256>>>(bufA, dg0, dt0, bufC, 512, 640);
    copy_yv_kernel<<<dim3(TLEN / 256, 128, BATCH), 256>>>(yv, bufC, 512, 640);

    launch_conv5(bufC, wt1, db1, bufA, 640, 1024);
    launch_gn_stats(bufA, 1024);
    gn_glu_kernel<<<dim3(TLEN / 256, 512, BATCH), 256>>>(bufA, dg1, dt1, bufC, 512, 640);
    copy_yv_kernel<<<dim3(TLEN / 256, 128, BATCH), 256>>>(yv, bufC, 512, 640);

    launch_conv5(bufC, wt2, db2, out, 640, 39);
}

// round 2
// speedup vs baseline: 1.7521x; 1.7521x over previous
#include <cuda_runtime.h>
#include <math.h>

#define BATCH 16
#define TLEN  2048
#define LRELU_SLOPE 0.02f
#define GN_EPS 1e-5

typedef unsigned long long u64;

// ---------------- scratch (no allocations allowed) ----------------
__device__ float  g_bufA[BATCH * 1024 * TLEN];   // 134 MB
__device__ float  g_bufB[BATCH * 512  * TLEN];   // 67 MB
__device__ float  g_bufC[BATCH * 640  * TLEN];   // 84 MB (concat buffers)
__device__ float  g_yv  [BATCH * 128  * TLEN];
__device__ float  g_z   [BATCH * 128  * TLEN];
__device__ float  g_spkn[64 * 128];
__device__ float  g_cbn [512 * 128];
// weights pre-transposed to [CI][K][CO]
__device__ float  g_we0 [39   * 5 * 1024];
__device__ float  g_we1 [1024 * 5 * 512];
__device__ float  g_we2 [512  * 5 * 512];
__device__ float  g_wm  [512  * 1 * 128];
__device__ float  g_wd0 [256  * 5 * 1024];
__device__ float  g_wd1 [640  * 5 * 1024];
__device__ float  g_wd2 [640  * 5 * 39];
__device__ double g_stats[2 * BATCH];

// ---------------- f32x2 packed-FMA helpers ----------------
__device__ __forceinline__ u64 pack2(float x) {
    u64 r; asm("mov.b64 %0, {%1, %1};" : "=l"(r) : "f"(x)); return r;
}
__device__ __forceinline__ u64 ffma2(u64 a, u64 b, u64 c) {
    u64 d; asm("fma.rn.f32x2 %0, %1, %2, %3;" : "=l"(d) : "l"(a), "l"(b), "l"(c));
    return d;
}
__device__ __forceinline__ float2 unpack2(u64 v) {
    float2 f; asm("mov.b64 {%0, %1}, %2;" : "=f"(f.x), "=f"(f.y) : "l"(v));
    return f;
}

// ---------------- weight transposes ----------------
// encoder Conv1d weight [CO][CI][K] -> [CI][K][CO]
__global__ void wenc_kernel(const float* __restrict__ W, float* __restrict__ Wp,
                            int CI, int CO, int K) {
    int idx = blockIdx.x * 256 + threadIdx.x;
    if (idx >= CO * CI * K) return;
    int k  = idx % K;
    int ci = (idx / K) % CI;
    int co = idx / (K * CI);
    Wp[((size_t)ci * K + k) * CO + co] = W[idx];
}
// decoder ConvTranspose weight [CI][CO][K] -> conv weight [CI][K(flipped)][CO]
__global__ void wdec_kernel(const float* __restrict__ W, float* __restrict__ Wp,
                            int CI, int CO, int K) {
    int idx = blockIdx.x * 256 + threadIdx.x;
    if (idx >= CO * CI * K) return;
    int k  = idx % K;
    int co = (idx / K) % CO;
    int ci = idx / (K * CO);
    Wp[((size_t)ci * K + (K - 1 - k)) * CO + co] = W[idx];
}

// ---------------- small helpers ----------------
__global__ void normalize_rows_kernel(const float* __restrict__ in,
                                      float* __restrict__ out) {
    int r = blockIdx.x, tid = threadIdx.x;
    float v = in[r * 128 + tid];
    __shared__ float sh[128];
    sh[tid] = v * v;
    __syncthreads();
    for (int off = 64; off > 0; off >>= 1) {
        if (tid < off) sh[tid] += sh[tid + off];
        __syncthreads();
    }
    out[r * 128 + tid] = v * rsqrtf(sh[0] + 1e-12f);
}

__global__ void gather_yv_kernel(const int* __restrict__ y,
                                 const float* __restrict__ spkn,
                                 float* __restrict__ yv) {
    int b = blockIdx.z, d = blockIdx.y;
    int t = blockIdx.x * 256 + threadIdx.x;
    int idx = y[b * TLEN + t];
    yv[((size_t)b * 128 + d) * TLEN + t] = spkn[idx * 128 + d];
}

__global__ void copy_yv_kernel(const float* __restrict__ yv,
                               float* __restrict__ cat, int off, int Ctot) {
    int b = blockIdx.z, d = blockIdx.y;
    int t = blockIdx.x * 256 + threadIdx.x;
    cat[((size_t)b * Ctot + off + d) * TLEN + t] =
        yv[((size_t)b * 128 + d) * TLEN + t];
}

__global__ void zero_stats_kernel() {
    if (threadIdx.x < 2 * BATCH) g_stats[threadIdx.x] = 0.0;
}

// ---------------- conv1d via FFMA2 SGEMM ----------------
// Block: 128(CO) x 128(T) output tile, 256 threads, 8x8 per thread,
// CI chunked by 8. Accumulators packed in f32x2 pairs along CO.
// Weights come from pre-transposed [CI][K][CO] global layout.
template <int K>
__global__ void __launch_bounds__(256, 2)
conv_f2_kernel(const float* __restrict__ X, const float* __restrict__ Wp,
               const float* __restrict__ bias, float* __restrict__ Y,
               int CI, int CO, int doStats) {
    const int BM = 128, BN = 128, BK = 8;
    const int PAD = (K - 1) / 2;
    const int XROW = BN + K - 1;
    const int NX = 8 + K - 1;

    __shared__ float Xs[BK][XROW];
    __shared__ float Ws[BK * K * BM];
    __shared__ float red1[8], red2[8];

    int b  = blockIdx.z;
    int t0 = blockIdx.x * BN;
    int o0 = blockIdx.y * BM;
    int tid = threadIdx.x;
    int warp = tid >> 5, lane = tid & 31;
    int wco = warp & 1, wt = warp >> 1;
    int lco = lane >> 2, lt = lane & 3;
    int tco = wco * 64 + lco * 8;   // CO base within tile
    int tt  = wt * 32 + lt * 8;     // T base within tile

    const float* Xb = X + (size_t)b * CI * TLEN;

    u64 acc[4][8];
#pragma unroll
    for (int p = 0; p < 4; p++)
#pragma unroll
        for (int j = 0; j < 8; j++) acc[p][j] = 0ull;

    for (int cb = 0; cb < CI; cb += BK) {
        // stage X tile (halo + zero pad)
        for (int i = tid; i < BK * XROW; i += 256) {
            int ci = i / XROW, t = i % XROW;
            int gci = cb + ci, gt = t0 + t - PAD;
            float v = 0.f;
            if (gci < CI && (unsigned)gt < (unsigned)TLEN)
                v = Xb[(size_t)gci * TLEN + gt];
            Xs[ci][t] = v;
        }
        // stage W tile: tile layout [ci][k][o] == contiguous slice of global [CI][K][CO]
        for (int i = tid; i < BK * K * BM; i += 256) {
            int ci = i / (K * BM);
            int r  = i % (K * BM);
            int k  = r / BM, o = r % BM;
            int gci = cb + ci, go = o0 + o;
            float v = 0.f;
            if (gci < CI && go < CO)
                v = Wp[((size_t)gci * K + k) * CO + go];
            Ws[i] = v;
        }
        __syncthreads();

#pragma unroll
        for (int ci = 0; ci < BK; ci++) {
            // load + splat the NX input values this thread needs
            u64 xs[NX];
#pragma unroll
            for (int v4 = 0; v4 < (NX + 3) / 4; v4++) {
                float4 xv = *(const float4*)&Xs[ci][tt + v4 * 4];
                if (v4 * 4 + 0 < NX) xs[v4 * 4 + 0] = pack2(xv.x);
                if (v4 * 4 + 1 < NX) xs[v4 * 4 + 1] = pack2(xv.y);
                if (v4 * 4 + 2 < NX) xs[v4 * 4 + 2] = pack2(xv.z);
                if (v4 * 4 + 3 < NX) xs[v4 * 4 + 3] = pack2(xv.w);
            }
#pragma unroll
            for (int k = 0; k < K; k++) {
                const float* wrow = &Ws[(ci * K + k) * BM + tco];
                ulonglong2 wa = *(const ulonglong2*)(wrow);
                ulonglong2 wb = *(const ulonglong2*)(wrow + 4);
                u64 wp[4] = {wa.x, wa.y, wb.x, wb.y};
#pragma unroll
                for (int p = 0; p < 4; p++)
#pragma unroll
                    for (int j = 0; j < 8; j++)
                        acc[p][j] = ffma2(wp[p], xs[j + k], acc[p][j]);
            }
        }
        __syncthreads();
    }

    // epilogue: bias add, store, fused GN stats
    int gt = t0 + tt;
    float ssum = 0.f, ssq = 0.f;
#pragma unroll
    for (int p = 0; p < 4; p++) {
        int oa = o0 + tco + 2 * p;
        int ob = oa + 1;
        bool va = oa < CO, vb = ob < CO;
        float ba = va ? bias[oa] : 0.f;
        float bb = vb ? bias[ob] : 0.f;
        float* rowa = Y + ((size_t)b * CO + oa) * TLEN;
        float* rowb = Y + ((size_t)b * CO + ob) * TLEN;
#pragma unroll
        for (int j = 0; j < 8; j++) {
            float2 v = unpack2(acc[p][j]);
            float fa = v.x + ba, fb = v.y + bb;
            if (va) { rowa[gt + j] = fa; ssum += fa; ssq += fa * fa; }
            if (vb) { rowb[gt + j] = fb; ssum += fb; ssq += fb * fb; }
        }
    }
    if (doStats) {
#pragma unroll
        for (int off = 16; off > 0; off >>= 1) {
            ssum += __shfl_down_sync(0xffffffffu, ssum, off);
            ssq  += __shfl_down_sync(0xffffffffu, ssq,  off);
        }
        if (lane == 0) { red1[warp] = ssum; red2[warp] = ssq; }
        __syncthreads();
        if (tid == 0) {
            double s = 0.0, s2 = 0.0;
            for (int w = 0; w < 8; w++) { s += red1[w]; s2 += red2[w]; }
            atomicAdd(&g_stats[2 * b],     s);
            atomicAdd(&g_stats[2 * b + 1], s2);
        }
    }
}

// ---------------- GroupNorm consumers ----------------
__global__ void gn_lrelu_kernel(float* __restrict__ X,
                                const float* __restrict__ g,
                                const float* __restrict__ bt, int C) {
    int b = blockIdx.z, c = blockIdx.y;
    int t = blockIdx.x * 256 + threadIdx.x;
    double N = (double)C * TLEN;
    double mean = g_stats[2 * b] / N;
    double var  = g_stats[2 * b + 1] / N - mean * mean;
    float rstd = (float)rsqrt(var + GN_EPS);
    float sc = g[c] * rstd;
    float sh = bt[c] - (float)mean * sc;
    size_t idx = ((size_t)b * C + c) * TLEN + t;
    float yv = X[idx] * sc + sh;
    X[idx] = yv >= 0.f ? yv : LRELU_SLOPE * yv;
}

__global__ void gn_glu_kernel(const float* __restrict__ X,
                              const float* __restrict__ g,
                              const float* __restrict__ bt,
                              float* __restrict__ cat, int H, int Ctot) {
    int b = blockIdx.z, c = blockIdx.y;
    int t = blockIdx.x * 256 + threadIdx.x;
    int C = 2 * H;
    double N = (double)C * TLEN;
    double mean = g_stats[2 * b] / N;
    double var  = g_stats[2 * b + 1] / N - mean * mean;
    float rstd = (float)rsqrt(var + GN_EPS);
    float m = (float)mean;
    float a  = X[((size_t)b * C + c)     * TLEN + t];
    float gv = X[((size_t)b * C + c + H) * TLEN + t];
    float na = (a  - m) * rstd * g[c]     + bt[c];
    float ng = (gv - m) * rstd * g[c + H] + bt[c + H];
    cat[((size_t)b * Ctot + c) * TLEN + t] = na / (1.f + expf(-ng));
}

// ---------------- VQ ----------------
__global__ void vq_kernel(const float* __restrict__ z,
                          const float* __restrict__ cbn,
                          float* __restrict__ cat, int Ctot) {
    __shared__ float zs[8][128];
    int warp = threadIdx.x >> 5, lane = threadIdx.x & 31;
    int pos = blockIdx.x * 8 + warp;
    int b = pos / TLEN, t = pos % TLEN;

    for (int d = lane; d < 128; d += 32)
        zs[warp][d] = z[((size_t)b * 128 + d) * TLEN + t];
    __syncwarp();

    const float4* zs4 = (const float4*)zs[warp];
    float best = -1e30f;
    int bk = 0;
    for (int kk = 0; kk < 16; kk++) {
        int k = kk * 32 + lane;
        const float4* cb4 = (const float4*)(cbn + (size_t)k * 128);
        float s = 0.f;
#pragma unroll
        for (int d4 = 0; d4 < 32; d4++) {
            float4 zv = zs4[d4], cv = cb4[d4];
            s += zv.x * cv.x + zv.y * cv.y + zv.z * cv.z + zv.w * cv.w;
        }
        if (s > best || (s == best && k < bk)) { best = s; bk = k; }
    }
    for (int off = 16; off > 0; off >>= 1) {
        float ob = __shfl_down_sync(0xffffffff, best, off);
        int   ok = __shfl_down_sync(0xffffffff, bk,   off);
        if (ob > best || (ob == best && ok < bk)) { best = ob; bk = ok; }
    }
    bk = __shfl_sync(0xffffffff, bk, 0);
    for (int d = lane; d < 128; d += 32)
        cat[((size_t)b * Ctot + d) * TLEN + t] = cbn[(size_t)bk * 128 + d];
}

// ---------------- host orchestration ----------------
static void launch_conv(const float* X, const float* Wp, const float* b,
                        float* Y, int CI, int CO, int K, int doStats) {
    dim3 grid(TLEN / 128, (CO + 127) / 128, BATCH);
    if (doStats) zero_stats_kernel<<<1, 32>>>();
    if (K == 5) conv_f2_kernel<5><<<grid, 256>>>(X, Wp, b, Y, CI, CO, doStats);
    else        conv_f2_kernel<1><<<grid, 256>>>(X, Wp, b, Y, CI, CO, doStats);
}

extern "C" void kernel_launch(void* const* d_in, const int* in_sizes, int n_in,
                              void* d_out, int out_size) {
    const float* x    = (const float*)d_in[0];
    const int*   y    = (const int*)  d_in[1];
    const float* spk  = (const float*)d_in[2];
    const float* cb   = (const float*)d_in[3];
    const float *ew0 = (const float*)d_in[4],  *eb0 = (const float*)d_in[5];
    const float *eg0 = (const float*)d_in[6],  *et0 = (const float*)d_in[7];
    const float *ew1 = (const float*)d_in[8],  *eb1 = (const float*)d_in[9];
    const float *eg1 = (const float*)d_in[10], *et1 = (const float*)d_in[11];
    const float *ew2 = (const float*)d_in[12], *eb2 = (const float*)d_in[13];
    const float *eg2 = (const float*)d_in[14], *et2 = (const float*)d_in[15];
    const float *mw  = (const float*)d_in[16], *mb  = (const float*)d_in[17];
    const float *dw0 = (const float*)d_in[18], *db0 = (const float*)d_in[19];
    const float *dg0 = (const float*)d_in[20], *dt0 = (const float*)d_in[21];
    const float *dw1 = (const float*)d_in[22], *db1 = (const float*)d_in[23];
    const float *dg1 = (const float*)d_in[24], *dt1 = (const float*)d_in[25];
    const float *dw2 = (const float*)d_in[26], *db2 = (const float*)d_in[27];
    float* out = (float*)d_out;

    float *bufA, *bufB, *bufC, *yv, *z, *spkn, *cbn;
    float *we0, *we1, *we2, *wm, *wd0, *wd1, *wd2;
    cudaGetSymbolAddress((void**)&bufA, g_bufA);
    cudaGetSymbolAddress((void**)&bufB, g_bufB);
    cudaGetSymbolAddress((void**)&bufC, g_bufC);
    cudaGetSymbolAddress((void**)&yv,   g_yv);
    cudaGetSymbolAddress((void**)&z,    g_z);
    cudaGetSymbolAddress((void**)&spkn, g_spkn);
    cudaGetSymbolAddress((void**)&cbn,  g_cbn);
    cudaGetSymbolAddress((void**)&we0,  g_we0);
    cudaGetSymbolAddress((void**)&we1,  g_we1);
    cudaGetSymbolAddress((void**)&we2,  g_we2);
    cudaGetSymbolAddress((void**)&wm,   g_wm);
    cudaGetSymbolAddress((void**)&wd0,  g_wd0);
    cudaGetSymbolAddress((void**)&wd1,  g_wd1);
    cudaGetSymbolAddress((void**)&wd2,  g_wd2);

    // ---- prep ----
    normalize_rows_kernel<<<64, 128>>>(spk, spkn);
    normalize_rows_kernel<<<512, 128>>>(cb, cbn);
    gather_yv_kernel<<<dim3(TLEN / 256, 128, BATCH), 256>>>(y, spkn, yv);
    wenc_kernel<<<(1024 * 39 * 5 + 255) / 256, 256>>>(ew0, we0, 39, 1024, 5);
    wenc_kernel<<<(512 * 1024 * 5 + 255) / 256, 256>>>(ew1, we1, 1024, 512, 5);
    wenc_kernel<<<(512 * 512 * 5 + 255) / 256, 256>>>(ew2, we2, 512, 512, 5);
    wenc_kernel<<<(128 * 512 + 255) / 256, 256>>>(mw, wm, 512, 128, 1);
    wdec_kernel<<<(256 * 1024 * 5 + 255) / 256, 256>>>(dw0, wd0, 256, 1024, 5);
    wdec_kernel<<<(640 * 1024 * 5 + 255) / 256, 256>>>(dw1, wd1, 640, 1024, 5);
    wdec_kernel<<<(640 * 39 * 5 + 255) / 256, 256>>>(dw2, wd2, 640, 39, 5);

    // ---- encoder ----
    launch_conv(x, we0, eb0, bufA, 39, 1024, 5, 1);
    gn_lrelu_kernel<<<dim3(TLEN / 256, 1024, BATCH), 256>>>(bufA, eg0, et0, 1024);

    launch_conv(bufA, we1, eb1, bufB, 1024, 512, 5, 1);
    gn_lrelu_kernel<<<dim3(TLEN / 256, 512, BATCH), 256>>>(bufB, eg1, et1, 512);

    launch_conv(bufB, we2, eb2, bufA, 512, 512, 5, 1);
    gn_lrelu_kernel<<<dim3(TLEN / 256, 512, BATCH), 256>>>(bufA, eg2, et2, 512);

    // 1x1 conv to latent
    launch_conv(bufA, wm, mb, z, 512, 128, 1, 0);

    // ---- VQ + concat speaker cond -> [B,256,T] ----
    vq_kernel<<<BATCH * TLEN / 8, 256>>>(z, cbn, bufC, 256);
    copy_yv_kernel<<<dim3(TLEN / 256, 128, BATCH), 256>>>(yv, bufC, 128, 256);

    // ---- decoder ----
    launch_conv(bufC, wd0, db0, bufA, 256, 1024, 5, 1);
    gn_glu_kernel<<<dim3(TLEN / 256, 512, BATCH), 256>>>(bufA, dg0, dt0, bufC, 512, 640);
    copy_yv_kernel<<<dim3(TLEN / 256, 128, BATCH), 256>>>(yv, bufC, 512, 640);

    launch_conv(bufC, wd1, db1, bufA, 640, 1024, 5, 1);
    gn_glu_kernel<<<dim3(TLEN / 256, 512, BATCH), 256>>>(bufA, dg1, dt1, bufC, 512, 640);
    copy_yv_kernel<<<dim3(TLEN / 256, 128, BATCH), 256>>>(yv, bufC, 512, 640);

    launch_conv(bufC, wd2, db2, out, 640, 39, 5, 0);
}

// round 3
// speedup vs baseline: 1.8451x; 1.0531x over previous
#include <cuda_runtime.h>
#include <math.h>

#define BATCH 16
#define TLEN  2048
#define LRELU_SLOPE 0.02f
#define GN_EPS 1e-5

typedef unsigned long long u64;

// ---------------- scratch (no allocations allowed) ----------------
__device__ float  g_bufA[BATCH * 1024 * TLEN];   // 134 MB
__device__ float  g_bufB[BATCH * 512  * TLEN];   // 67 MB
__device__ float  g_bufC[BATCH * 640  * TLEN];   // cat: [yv(128) | payload(512)]
__device__ float  g_z   [BATCH * 128  * TLEN];
__device__ float  g_spkn[64 * 128];
__device__ float  g_cbn [512 * 128];
// weights pre-transposed to [CI][K][CO]
__device__ float  g_we0 [39   * 5 * 1024];
__device__ float  g_we1 [1024 * 5 * 512];
__device__ float  g_we2 [512  * 5 * 512];
__device__ float  g_wm  [512  * 1 * 128];
__device__ float  g_wd0 [256  * 5 * 1024];
__device__ float  g_wd1 [640  * 5 * 1024];
__device__ float  g_wd2 [640  * 5 * 39];
__device__ double g_stats[2 * BATCH];

// ---------------- f32x2 packed-FMA helpers ----------------
__device__ __forceinline__ u64 pack2(float x) {
    u64 r; asm("mov.b64 %0, {%1, %1};" : "=l"(r) : "f"(x)); return r;
}
__device__ __forceinline__ u64 ffma2(u64 a, u64 b, u64 c) {
    u64 d; asm("fma.rn.f32x2 %0, %1, %2, %3;" : "=l"(d) : "l"(a), "l"(b), "l"(c));
    return d;
}
__device__ __forceinline__ float2 unpack2(u64 v) {
    float2 f; asm("mov.b64 {%0, %1}, %2;" : "=f"(f.x), "=f"(f.y) : "l"(v));
    return f;
}

// ---------------- cp.async helpers ----------------
__device__ __forceinline__ void cp_async4(float* smem, const float* g, bool p) {
    unsigned s = (unsigned)__cvta_generic_to_shared(smem);
    int sz = p ? 4 : 0;
    asm volatile("cp.async.ca.shared.global [%0], [%1], 4, %2;"
                 :: "r"(s), "l"(g), "r"(sz));
}
#define CP_COMMIT() asm volatile("cp.async.commit_group;" ::: "memory")
#define CP_WAIT(n)  asm volatile("cp.async.wait_group %0;" :: "n"(n) : "memory")

// ---------------- weight transposes ----------------
// encoder Conv1d weight [CO][CI][K] -> [CI][K][CO]
__global__ void wenc_kernel(const float* __restrict__ W, float* __restrict__ Wp,
                            int CI, int CO, int K) {
    int idx = blockIdx.x * 256 + threadIdx.x;
    if (idx >= CO * CI * K) return;
    int k  = idx % K;
    int ci = (idx / K) % CI;
    int co = idx / (K * CI);
    Wp[((size_t)ci * K + k) * CO + co] = W[idx];
}
// decoder ConvTranspose weight [CI][CO][K] -> conv weight [CI'][K(flip)][CO],
// remapping CI so the cat buffer can be laid out [yv(128) | payload]:
//   old ci < split (payload) -> new ci + 128 ; old ci >= split (yv) -> ci - split
__global__ void wdec_kernel(const float* __restrict__ W, float* __restrict__ Wp,
                            int CI, int CO, int split) {
    int idx = blockIdx.x * 256 + threadIdx.x;
    if (idx >= CO * CI * 5) return;
    int k  = idx % 5;
    int co = (idx / 5) % CO;
    int ci = idx / (5 * CO);
    int cin = (ci < split) ? ci + 128 : ci - split;
    Wp[((size_t)cin * 5 + (4 - k)) * CO + co] = W[idx];
}

// ---------------- small helpers ----------------
__global__ void normalize_rows_kernel(const float* __restrict__ in,
                                      float* __restrict__ out) {
    int r = blockIdx.x, tid = threadIdx.x;
    float v = in[r * 128 + tid];
    __shared__ float sh[128];
    sh[tid] = v * v;
    __syncthreads();
    for (int off = 64; off > 0; off >>= 1) {
        if (tid < off) sh[tid] += sh[tid + off];
        __syncthreads();
    }
    out[r * 128 + tid] = v * rsqrtf(sh[0] + 1e-12f);
}

// speaker cond written once into cat channels [0,128)
__global__ void gather_yv_kernel(const int* __restrict__ y,
                                 const float* __restrict__ spkn,
                                 float* __restrict__ cat) {
    int b = blockIdx.z, d = blockIdx.y;
    int t = blockIdx.x * 256 + threadIdx.x;
    int idx = y[b * TLEN + t];
    cat[((size_t)b * 640 + d) * TLEN + t] = spkn[idx * 128 + d];
}

__global__ void zero_stats_kernel() {
    if (threadIdx.x < 2 * BATCH) g_stats[threadIdx.x] = 0.0;
}

// ---------------- conv1d via FFMA2 SGEMM, cp.async pipelined ----------------
// Block: 128(CO) x 128(T) tile, 256 threads, 8x8 per thread, CI chunks of 8,
// double-buffered smem staging. X row stride is CBx channels (cat support).
template <int K>
__device__ __forceinline__ void stage_tiles(
    const float* __restrict__ Xb, const float* __restrict__ Wp,
    float* XsBuf, float* WsBuf, int cb, int CI, int CO, int t0, int o0, int tid) {
    const int BM = 128, XR = 128 + (K - 1), PAD = (K - 1) / 2;
    for (int i = tid; i < 8 * XR; i += 256) {
        int ci = i / XR, t = i % XR;
        int gci = cb + ci, gt = t0 + t - PAD;
        bool p = (gci < CI) && ((unsigned)gt < (unsigned)TLEN);
        const float* src = p ? (Xb + (size_t)gci * TLEN + gt) : Xb;
        cp_async4(XsBuf + ci * XR + t, src, p);
    }
    for (int i = tid; i < 8 * K * BM; i += 256) {
        int ci = i / (K * BM);
        int r  = i % (K * BM);
        int k = r / BM, o = r % BM;
        int gci = cb + ci, go = o0 + o;
        bool p = (gci < CI) && (go < CO);
        const float* src = p ? (Wp + ((size_t)gci * K + k) * CO + go) : Wp;
        cp_async4(WsBuf + i, src, p);
    }
}

template <int K>
__global__ void __launch_bounds__(256, 2)
conv_f2_kernel(const float* __restrict__ X, const float* __restrict__ Wp,
               const float* __restrict__ bias, float* __restrict__ Y,
               int CI, int CBx, int CO, int doStats) {
    const int BM = 128, BN = 128, BK = 8;
    const int XR = BN + (K - 1);
    const int NX = 8 + K - 1;            // 12 (K=5) or 8 (K=1), both /4
    const int XSZ = BK * XR;
    const int WSZ = BK * K * BM;

    extern __shared__ float sm[];
    float* Xs0 = sm;                 // 2 * XSZ
    float* Ws0 = sm + 2 * XSZ;       // 2 * WSZ
    float* red = Ws0 + 2 * WSZ;      // 16

    int b  = blockIdx.z;
    int t0 = blockIdx.x * BN;
    int o0 = blockIdx.y * BM;
    int tid = threadIdx.x;
    int warp = tid >> 5, lane = tid & 31;
    int wco = warp & 1, wt = warp >> 1;
    int lco = lane >> 2, lt = lane & 3;
    int tco = wco * 64 + lco * 8;
    int tt  = wt * 32 + lt * 8;

    const float* Xb = X + (size_t)b * CBx * TLEN;
    int nchunk = (CI + BK - 1) / BK;

    u64 acc[4][8];
#pragma unroll
    for (int p = 0; p < 4; p++)
#pragma unroll
        for (int j = 0; j < 8; j++) acc[p][j] = 0ull;

    stage_tiles<K>(Xb, Wp, Xs0, Ws0, 0, CI, CO, t0, o0, tid);
    CP_COMMIT();

    for (int c = 0; c < nchunk; c++) {
        int buf = c & 1;
        if (c + 1 < nchunk) {
            stage_tiles<K>(Xb, Wp, Xs0 + (buf ^ 1) * XSZ, Ws0 + (buf ^ 1) * WSZ,
                           (c + 1) * BK, CI, CO, t0, o0, tid);
            CP_COMMIT();
            CP_WAIT(1);
        } else {
            CP_WAIT(0);
        }
        __syncthreads();

        const float* Xsb = Xs0 + buf * XSZ;
        const float* Wsb = Ws0 + buf * WSZ;
#pragma unroll
        for (int ci = 0; ci < BK; ci++) {
            u64 xs[NX];
            const float4* xrow = (const float4*)(Xsb + ci * XR + tt);
#pragma unroll
            for (int v4 = 0; v4 < NX / 4; v4++) {
                float4 xv = xrow[v4];
                xs[v4 * 4 + 0] = pack2(xv.x);
                xs[v4 * 4 + 1] = pack2(xv.y);
                xs[v4 * 4 + 2] = pack2(xv.z);
                xs[v4 * 4 + 3] = pack2(xv.w);
            }
#pragma unroll
            for (int k = 0; k < K; k++) {
                const float* wrow = Wsb + (ci * K + k) * BM + tco;
                ulonglong2 wa = *(const ulonglong2*)(wrow);
                ulonglong2 wb = *(const ulonglong2*)(wrow + 4);
                u64 wp[4] = {wa.x, wa.y, wb.x, wb.y};
#pragma unroll
                for (int p = 0; p < 4; p++)
#pragma unroll
                    for (int j = 0; j < 8; j++)
                        acc[p][j] = ffma2(wp[p], xs[j + k], acc[p][j]);
            }
        }
        __syncthreads();
    }

    // epilogue: bias, vectorized store, fused GN stats
    int gt = t0 + tt;
    float ssum = 0.f, ssq = 0.f;
#pragma unroll
    for (int p = 0; p < 4; p++) {
        int oa = o0 + tco + 2 * p;
        int ob = oa + 1;
        bool va = oa < CO, vb = ob < CO;
        float ba = va ? bias[oa] : 0.f;
        float bb = vb ? bias[ob] : 0.f;
        float fa[8], fb[8];
#pragma unroll
        for (int j = 0; j < 8; j++) {
            float2 v = unpack2(acc[p][j]);
            fa[j] = v.x + ba; fb[j] = v.y + bb;
            if (va) { ssum += fa[j]; ssq += fa[j] * fa[j]; }
            if (vb) { ssum += fb[j]; ssq += fb[j] * fb[j]; }
        }
        if (va) {
            float* rowa = Y + ((size_t)b * CO + oa) * TLEN + gt;
            *(float4*)(rowa)     = make_float4(fa[0], fa[1], fa[2], fa[3]);
            *(float4*)(rowa + 4) = make_float4(fa[4], fa[5], fa[6], fa[7]);
        }
        if (vb) {
            float* rowb = Y + ((size_t)b * CO + ob) * TLEN + gt;
            *(float4*)(rowb)     = make_float4(fb[0], fb[1], fb[2], fb[3]);
            *(float4*)(rowb + 4) = make_float4(fb[4], fb[5], fb[6], fb[7]);
        }
    }
    if (doStats) {
#pragma unroll
        for (int off = 16; off > 0; off >>= 1) {
            ssum += __shfl_down_sync(0xffffffffu, ssum, off);
            ssq  += __shfl_down_sync(0xffffffffu, ssq,  off);
        }
        if (lane == 0) { red[warp] = ssum; red[8 + warp] = ssq; }
        __syncthreads();
        if (tid == 0) {
            double s = 0.0, s2 = 0.0;
            for (int w = 0; w < 8; w++) { s += red[w]; s2 += red[8 + w]; }
            atomicAdd(&g_stats[2 * b],     s);
            atomicAdd(&g_stats[2 * b + 1], s2);
        }
    }
}

// ---------------- GroupNorm consumers ----------------
__global__ void gn_lrelu_kernel(float* __restrict__ X,
                                const float* __restrict__ g,
                                const float* __restrict__ bt, int C) {
    int b = blockIdx.z, c = blockIdx.y;
    int t = blockIdx.x * 256 + threadIdx.x;
    double N = (double)C * TLEN;
    double mean = g_stats[2 * b] / N;
    double var  = g_stats[2 * b + 1] / N - mean * mean;
    float rstd = (float)rsqrt(var + GN_EPS);
    float sc = g[c] * rstd;
    float sh = bt[c] - (float)mean * sc;
    size_t idx = ((size_t)b * C + c) * TLEN + t;
    float yv = X[idx] * sc + sh;
    X[idx] = yv >= 0.f ? yv : LRELU_SLOPE * yv;
}

// GroupNorm over 2H channels then GLU -> cat channels [128, 128+H)
__global__ void gn_glu_kernel(const float* __restrict__ X,
                              const float* __restrict__ g,
                              const float* __restrict__ bt,
                              float* __restrict__ cat, int H) {
    int b = blockIdx.z, c = blockIdx.y;
    int t = blockIdx.x * 256 + threadIdx.x;
    int C = 2 * H;
    double N = (double)C * TLEN;
    double mean = g_stats[2 * b] / N;
    double var  = g_stats[2 * b + 1] / N - mean * mean;
    float rstd = (float)rsqrt(var + GN_EPS);
    float m = (float)mean;
    float a  = X[((size_t)b * C + c)     * TLEN + t];
    float gv = X[((size_t)b * C + c + H) * TLEN + t];
    float na = (a  - m) * rstd * g[c]     + bt[c];
    float ng = (gv - m) * rstd * g[c + H] + bt[c + H];
    cat[((size_t)b * 640 + 128 + c) * TLEN + t] = na / (1.f + expf(-ng));
}

// ---------------- VQ: writes cbn[k*] into cat channels [128,256) ----------------
__global__ void vq_kernel(const float* __restrict__ z,
                          const float* __restrict__ cbn,
                          float* __restrict__ cat) {
    __shared__ float zs[8][128];
    int warp = threadIdx.x >> 5, lane = threadIdx.x & 31;
    int pos = blockIdx.x * 8 + warp;
    int b = pos / TLEN, t = pos % TLEN;

    for (int d = lane; d < 128; d += 32)
        zs[warp][d] = z[((size_t)b * 128 + d) * TLEN + t];
    __syncwarp();

    const float4* zs4 = (const float4*)zs[warp];
    float best = -1e30f;
    int bk = 0;
    for (int kk = 0; kk < 16; kk++) {
        int k = kk * 32 + lane;
        const float4* cb4 = (const float4*)(cbn + (size_t)k * 128);
        float s = 0.f;
#pragma unroll
        for (int d4 = 0; d4 < 32; d4++) {
            float4 zv = zs4[d4], cv = cb4[d4];
            s += zv.x * cv.x + zv.y * cv.y + zv.z * cv.z + zv.w * cv.w;
        }
        if (s > best || (s == best && k < bk)) { best = s; bk = k; }
    }
    for (int off = 16; off > 0; off >>= 1) {
        float ob = __shfl_down_sync(0xffffffff, best, off);
        int   ok = __shfl_down_sync(0xffffffff, bk,   off);
        if (ob > best || (ob == best && ok < bk)) { best = ob; bk = ok; }
    }
    bk = __shfl_sync(0xffffffff, bk, 0);
    for (int d = lane; d < 128; d += 32)
        cat[((size_t)b * 640 + 128 + d) * TLEN + t] = cbn[(size_t)bk * 128 + d];
}

// ---------------- host orchestration ----------------
static const int SMEM_K5 = (2 * (8 * 132) + 2 * (8 * 5 * 128) + 16) * 4; // 49472
static const int SMEM_K1 = (2 * (8 * 128) + 2 * (8 * 1 * 128) + 16) * 4; // 16448

static void launch_conv(const float* X, const float* Wp, const float* b,
                        float* Y, int CI, int CBx, int CO, int K, int doStats) {
    dim3 grid(TLEN / 128, (CO + 127) / 128, BATCH);
    if (doStats) zero_stats_kernel<<<1, 32>>>();
    if (K == 5)
        conv_f2_kernel<5><<<grid, 256, SMEM_K5>>>(X, Wp, b, Y, CI, CBx, CO, doStats);
    else
        conv_f2_kernel<1><<<grid, 256, SMEM_K1>>>(X, Wp, b, Y, CI, CBx, CO, doStats);
}

extern "C" void kernel_launch(void* const* d_in, const int* in_sizes, int n_in,
                              void* d_out, int out_size) {
    const float* x    = (const float*)d_in[0];
    const int*   y    = (const int*)  d_in[1];
    const float* spk  = (const float*)d_in[2];
    const float* cb   = (const float*)d_in[3];
    const float *ew0 = (const float*)d_in[4],  *eb0 = (const float*)d_in[5];
    const float *eg0 = (const float*)d_in[6],  *et0 = (const float*)d_in[7];
    const float *ew1 = (const float*)d_in[8],  *eb1 = (const float*)d_in[9];
    const float *eg1 = (const float*)d_in[10], *et1 = (const float*)d_in[11];
    const float *ew2 = (const float*)d_in[12], *eb2 = (const float*)d_in[13];
    const float *eg2 = (const float*)d_in[14], *et2 = (const float*)d_in[15];
    const float *mw  = (const float*)d_in[16], *mb  = (const float*)d_in[17];
    const float *dw0 = (const float*)d_in[18], *db0 = (const float*)d_in[19];
    const float *dg0 = (const float*)d_in[20], *dt0 = (const float*)d_in[21];
    const float *dw1 = (const float*)d_in[22], *db1 = (const float*)d_in[23];
    const float *dg1 = (const float*)d_in[24], *dt1 = (const float*)d_in[25];
    const float *dw2 = (const float*)d_in[26], *db2 = (const float*)d_in[27];
    float* out = (float*)d_out;

    cudaFuncSetAttribute(conv_f2_kernel<5>,
                         cudaFuncAttributeMaxDynamicSharedMemorySize, SMEM_K5);
    cudaFuncSetAttribute(conv_f2_kernel<1>,
                         cudaFuncAttributeMaxDynamicSharedMemorySize, SMEM_K1);

    float *bufA, *bufB, *bufC, *z, *spkn, *cbn;
    float *we0, *we1, *we2, *wm, *wd0, *wd1, *wd2;
    cudaGetSymbolAddress((void**)&bufA, g_bufA);
    cudaGetSymbolAddress((void**)&bufB, g_bufB);
    cudaGetSymbolAddress((void**)&bufC, g_bufC);
    cudaGetSymbolAddress((void**)&z,    g_z);
    cudaGetSymbolAddress((void**)&spkn, g_spkn);
    cudaGetSymbolAddress((void**)&cbn,  g_cbn);
    cudaGetSymbolAddress((void**)&we0,  g_we0);
    cudaGetSymbolAddress((void**)&we1,  g_we1);
    cudaGetSymbolAddress((void**)&we2,  g_we2);
    cudaGetSymbolAddress((void**)&wm,   g_wm);
    cudaGetSymbolAddress((void**)&wd0,  g_wd0);
    cudaGetSymbolAddress((void**)&wd1,  g_wd1);
    cudaGetSymbolAddress((void**)&wd2,  g_wd2);

    // ---- prep ----
    normalize_rows_kernel<<<64, 128>>>(spk, spkn);
    normalize_rows_kernel<<<512, 128>>>(cb, cbn);
    gather_yv_kernel<<<dim3(TLEN / 256, 128, BATCH), 256>>>(y, spkn, bufC);
    wenc_kernel<<<(1024 * 39 * 5 + 255) / 256, 256>>>(ew0, we0, 39, 1024, 5);
    wenc_kernel<<<(512 * 1024 * 5 + 255) / 256, 256>>>(ew1, we1, 1024, 512, 5);
    wenc_kernel<<<(512 * 512 * 5 + 255) / 256, 256>>>(ew2, we2, 512, 512, 5);
    wenc_kernel<<<(128 * 512 + 255) / 256, 256>>>(mw, wm, 512, 128, 1);
    wdec_kernel<<<(256 * 1024 * 5 + 255) / 256, 256>>>(dw0, wd0, 256, 1024, 128);
    wdec_kernel<<<(640 * 1024 * 5 + 255) / 256, 256>>>(dw1, wd1, 640, 1024, 512);
    wdec_kernel<<<(640 * 39 * 5 + 255) / 256, 256>>>(dw2, wd2, 640, 39, 512);

    // ---- encoder ----
    launch_conv(x, we0, eb0, bufA, 39, 39, 1024, 5, 1);
    gn_lrelu_kernel<<<dim3(TLEN / 256, 1024, BATCH), 256>>>(bufA, eg0, et0, 1024);

    launch_conv(bufA, we1, eb1, bufB, 1024, 1024, 512, 5, 1);
    gn_lrelu_kernel<<<dim3(TLEN / 256, 512, BATCH), 256>>>(bufB, eg1, et1, 512);

    launch_conv(bufB, we2, eb2, bufA, 512, 512, 512, 5, 1);
    gn_lrelu_kernel<<<dim3(TLEN / 256, 512, BATCH), 256>>>(bufA, eg2, et2, 512);

    // 1x1 conv to latent
    launch_conv(bufA, wm, mb, z, 512, 512, 128, 1, 0);

    // ---- VQ -> cat [yv | zq] ----
    vq_kernel<<<BATCH * TLEN / 8, 256>>>(z, cbn, bufC);

    // ---- decoder ----
    launch_conv(bufC, wd0, db0, bufA, 256, 640, 1024, 5, 1);
    gn_glu_kernel<<<dim3(TLEN / 256, 512, BATCH), 256>>>(bufA, dg0, dt0, bufC, 512);

    launch_conv(bufC, wd1, db1, bufA, 640, 640, 1024, 5, 1);
    gn_glu_kernel<<<dim3(TLEN / 256, 512, BATCH), 256>>>(bufA, dg1, dt1, bufC, 512);

    launch_conv(bufC, wd2, db2, out, 640, 640, 39, 5, 0);
}